// round 17
// baseline (speedup 1.0000x reference)
#include <cuda_runtime.h>
#include <math.h>

// ---------------- problem constants ----------------
#define TT      4000          // N_WORDS (sequence length)
#define NCHARS  16000
#define DCHAR   768
#define HH      400           // hidden size
#define KCTA    50            // CTAs per LSTM direction
#define HS      8             // h elements per CTA (one per compute warp)
#define NT      384           // 4 poller warps (wid 0-3) + 8 compute warps (wid 4-11)
#define TAG_BOUND (1u << 16)  // bounded spin (hang -> wrong answer, not timeout)

// ---------------- device scratch (static, no allocation) ----------------
__device__ float g_ef[TT * 868];        // [wc(768) | pos(100)]
__device__ float g_l1[TT * 800];        // layer-1 output [f1 | flip(f2)]
__device__ float g_PF[TT * 1600];       // x-projection, forward dir
__device__ float g_PB[TT * 1600];       // x-projection, backward dir
__device__ float g_mean[TT * DCHAR];    // chars_mean
// tagged h broadcast: 4 sets (F1,B1,F2,B2) x 2 parities x 400 elements
__device__ __align__(16) unsigned long long g_hb[4 * 2 * HH];

// ---------------- k_mean: binary-search starts + segment mean + zero g_hb ----
__global__ void k_mean(const float* __restrict__ chem, const int* __restrict__ seg) {
    int w = blockIdx.x, tid = threadIdx.x;
    if (w < 13) {                       // zero broadcast buffers
        int i = w * 256 + tid;
        if (i < 4 * 2 * HH) g_hb[i] = 0ULL;
    }
    __shared__ int se[2];
    if (tid < 2) {
        int target = w + tid;           // lower_bound(seg, target)
        int lo = 0, hi = NCHARS;
        while (lo < hi) { int m = (lo + hi) >> 1; if (seg[m] < target) lo = m + 1; else hi = m; }
        se[tid] = lo;
    }
    __syncthreads();
    int s = se[0], e = se[1];
    float inv = 1.f / (float)(e - s);
    for (int d = tid; d < DCHAR; d += blockDim.x) {
        float acc = 0.f;
        for (int r = s; r < e; r++) acc += chem[(size_t)(r + 1) * DCHAR + d];
        g_mean[(size_t)w * DCHAR + d] = acc * inv;
    }
}

// ---------------- fp32 GEMM (R4-proven): C[m,n] = dot(A[m,:], B[n,:]) + bias[n] ----
__global__ void __launch_bounds__(256, 2) k_gemm(
    int M, int N, int Ka,
    const float* __restrict__ A, int lda, const int* __restrict__ Aidx,
    const float* __restrict__ B0, const float* __restrict__ bias0, float* __restrict__ C0,
    const float* __restrict__ B1, const float* __restrict__ bias1, float* __restrict__ C1,
    int ldc, const float* __restrict__ extra, int mode,
    const int* __restrict__ pos_seq, const float* __restrict__ pos_table)
{
    if (mode == 1 && blockIdx.z == 1) {
        int nb = gridDim.x * gridDim.y;
        int bid = blockIdx.y * gridDim.x + blockIdx.x;
        for (int i = bid * 256 + threadIdx.x; i < TT * 100; i += nb * 256) {
            int m = i / 100, j = i - m * 100;
            g_ef[(size_t)m * 868 + 768 + j] = pos_table[pos_seq[m] * 100 + j];
        }
        return;
    }
    const float* B    = blockIdx.z ? B1    : B0;
    const float* bias = blockIdx.z ? bias1 : bias0;
    float*       C    = blockIdx.z ? C1    : C0;

    __shared__ float As[16][132];
    __shared__ float Bs[16][132];
    int tid = threadIdx.x;
    int tx = tid & 15, ty = tid >> 4;
    int m0 = blockIdx.y * 128, n0 = blockIdx.x * 128;
    int lr = tid >> 2;
    int lk = (tid & 3) * 4;

    float acc[8][8];
#pragma unroll
    for (int i = 0; i < 8; i++)
#pragma unroll
        for (int j = 0; j < 8; j++) acc[i][j] = 0.f;

    for (int kt = 0; kt < Ka; kt += 16) {
#pragma unroll
        for (int p = 0; p < 2; p++) {
            int m = lr + p * 64; int gm = m0 + m;
            float4 v = make_float4(0.f, 0.f, 0.f, 0.f);
            if (gm < M && kt + lk < Ka) {
                int ar = Aidx ? Aidx[gm] : gm;
                v = *(const float4*)&A[(size_t)ar * lda + kt + lk];
            }
            As[lk + 0][m] = v.x; As[lk + 1][m] = v.y;
            As[lk + 2][m] = v.z; As[lk + 3][m] = v.w;
        }
#pragma unroll
        for (int p = 0; p < 2; p++) {
            int n = lr + p * 64; int gn = n0 + n;
            float4 v = make_float4(0.f, 0.f, 0.f, 0.f);
            if (gn < N && kt + lk < Ka) {
                v = *(const float4*)&B[(size_t)gn * Ka + kt + lk];
            }
            Bs[lk + 0][n] = v.x; Bs[lk + 1][n] = v.y;
            Bs[lk + 2][n] = v.z; Bs[lk + 3][n] = v.w;
        }
        __syncthreads();
#pragma unroll
        for (int kk = 0; kk < 16; kk++) {
            float a[8], b[8];
            *(float4*)&a[0] = *(const float4*)&As[kk][ty * 8];
            *(float4*)&a[4] = *(const float4*)&As[kk][ty * 8 + 4];
            *(float4*)&b[0] = *(const float4*)&Bs[kk][tx * 8];
            *(float4*)&b[4] = *(const float4*)&Bs[kk][tx * 8 + 4];
#pragma unroll
            for (int i = 0; i < 8; i++)
#pragma unroll
                for (int j = 0; j < 8; j++) acc[i][j] += a[i] * b[j];
        }
        __syncthreads();
    }
#pragma unroll
    for (int i = 0; i < 8; i++) {
        int m = m0 + ty * 8 + i;
        if (m < M) {
#pragma unroll
            for (int j = 0; j < 8; j++) {
                int n = n0 + tx * 8 + j;
                if (n < N) {
                    float v = acc[i][j] + bias[n];
                    if (mode == 1) v = tanhf(v) + extra[(size_t)m * DCHAR + n];
                    C[(size_t)m * ldc + n] = v;
                }
            }
        }
    }
}

// ---------------- persistent bidirectional LSTM recurrence ----------------
// Warps 4-11: EXACT round-4 compute datapath (warp w-4 owns element e=k*8+w-4,
//   4-gate dot, 5-stage butterfly, parallel gate nonlinearities on lanes 0-3,
//   lane 0 publishes the tagged packet FIRST, then layer output).
// Warps 0-3 (LOW wid -> lose arbitration to compute warps): dedicated pollers,
//   loads continuously in flight from step start; thread t polls elements
//   t, t+128, t+256 (+t+384 if t<16) and fills the next h buffer.
__global__ void __launch_bounds__(NT, 1) k_lstm(
    const float* __restrict__ Pf, const float* __restrict__ Whhf,
    const float* __restrict__ h0f, const float* __restrict__ c0f,
    float* outf, int ldf, int colf, int flinf, int floutf, unsigned long long* hbf,
    const float* __restrict__ Pb, const float* __restrict__ Whhb,
    const float* __restrict__ h0b, const float* __restrict__ c0b,
    float* outb, int ldb, int colb, int flinb, int floutb, unsigned long long* hbb)
{
    int dir = blockIdx.x >= KCTA;
    int k   = blockIdx.x - dir * KCTA;
    const float* P   = dir ? Pb   : Pf;
    const float* Whh = dir ? Whhb : Whhf;
    const float* h0  = dir ? h0b  : h0f;
    const float* c0  = dir ? c0b  : c0f;
    float* outbase   = dir ? outb : outf;
    int ld    = dir ? ldb    : ldf;
    int col   = dir ? colb   : colf;
    int flin  = dir ? flinb  : flinf;
    int flout = dir ? floutb : floutf;
    unsigned long long* hb = dir ? hbb : hbf;

    __shared__ float hbuf[2][416];   // double-buffered h (tail zero)

    int tid = threadIdx.x, lane = tid & 31, wid = tid >> 5;

    for (int i = tid; i < 416; i += NT) {
        hbuf[0][i] = (i < HH) ? h0[i] : 0.f;
        hbuf[1][i] = 0.f;
    }

    if (wid >= 4) {
        // ================= compute warps (round-4 datapath) =================
        int w = wid - 4;                 // 0..7
        int e = k * HS + w;

        float creg = 0.f;
        if (lane == 0) creg = c0[e];

        float wreg[4][13];
#pragma unroll
        for (int q = 0; q < 4; q++) {
            const float* wp = Whh + (size_t)(q * HH + e) * HH;
#pragma unroll
            for (int j = 0; j < 13; j++) {
                int cc = j * 32 + lane;
                wreg[q][j] = (cc < HH) ? wp[cc] : 0.f;
            }
        }

        // x-projection for step 0: lane q (q<4) holds gate-q term
        float xcur = 0.f;
        if (lane < 4) {
            int row = flin ? (TT - 1) : 0;
            xcur = P[(size_t)row * 1600 + lane * HH + e];
        }
        __syncthreads();

        for (int s = 0; s < TT; s++) {
            // prefetch next step's x
            float xn = 0.f;
            if (lane < 4 && s + 1 < TT) {
                int row = flin ? (TT - 2 - s) : (s + 1);
                xn = P[(size_t)row * 1600 + lane * HH + e];
            }

            const float* cur = hbuf[s & 1];
            float* nxt = hbuf[(s + 1) & 1];

            // GEMV: 4 gate rows x 400 (weights in regs, h from smem)
            float a0 = 0.f, a1 = 0.f, a2 = 0.f, a3 = 0.f;
#pragma unroll
            for (int j = 0; j < 13; j++) {
                float hv = cur[j * 32 + lane];
                a0 += wreg[0][j] * hv;
                a1 += wreg[1][j] * hv;
                a2 += wreg[2][j] * hv;
                a3 += wreg[3][j] * hv;
            }
#pragma unroll
            for (int d = 16; d > 0; d >>= 1) {
                a0 += __shfl_xor_sync(0xffffffffu, a0, d);
                a1 += __shfl_xor_sync(0xffffffffu, a1, d);
                a2 += __shfl_xor_sync(0xffffffffu, a2, d);
                a3 += __shfl_xor_sync(0xffffffffu, a3, d);
            }

            // lane q (0..3) applies gate-q nonlinearity
            float zsel = (lane & 2) ? ((lane & 1) ? a3 : a2)
                                    : ((lane & 1) ? a1 : a0);
            float z = zsel + xcur;
            float earg = (lane == 2) ? (-2.f * z) : (-z);
            float r = 1.f / (1.f + __expf(earg));
            float nl = (lane == 2) ? (2.f * r - 1.f) : r;   // tanh for g, sigmoid else

            float gi = __shfl_sync(0xffffffffu, nl, 0);
            float gf = __shfl_sync(0xffffffffu, nl, 1);
            float gg = __shfl_sync(0xffffffffu, nl, 2);
            float go = __shfl_sync(0xffffffffu, nl, 3);

            int orow = flout ? (TT - 1 - s) : s;
            if (lane == 0) {
                float c = gf * creg + gi * gg;
                creg = c;
                float th = 2.f / (1.f + __expf(-2.f * c)) - 1.f;
                float h = go * th;
                if (s + 1 < TT) {                // publish FIRST
                    unsigned long long pk =
                        ((unsigned long long)(unsigned)(s + 1) << 32) |
                        (unsigned long long)__float_as_uint(h);
                    unsigned long long* dst = hb + (size_t)(s & 1) * HH + e;
                    asm volatile("st.relaxed.gpu.global.b64 [%0], %1;"
                                 :: "l"(dst), "l"(pk) : "memory");
                    nxt[e] = h;                  // own slice locally
                }
                outbase[(size_t)orow * ld + col + e] = h;
            }
            xcur = xn;
            __syncthreads();   // pollers have filled nxt
        }
    } else {
        // ================= poller warps (LOW wid: never outrank compute) ====
        int t = tid;                    // 0..127
        int e0 = t, e1 = t + 128, e2 = t + 256, e3 = t + 384;
        bool four = (e3 < HH);          // t < 16 handles a 4th element
        __syncthreads();

        for (int s = 0; s < TT; s++) {
            if (s + 1 < TT) {
                const unsigned long long* sp = hb + (size_t)(s & 1) * HH;
                float* nxt = hbuf[(s + 1) & 1];
                unsigned tgt = (unsigned)(s + 1);
                unsigned long long v0, v1, v2, v3 = 0;
                if (four) {
                    for (unsigned it = 0; it < TAG_BOUND; it++) {
                        asm volatile(
                            "ld.relaxed.gpu.global.b64 %0, [%4];\n\t"
                            "ld.relaxed.gpu.global.b64 %1, [%5];\n\t"
                            "ld.relaxed.gpu.global.b64 %2, [%6];\n\t"
                            "ld.relaxed.gpu.global.b64 %3, [%7];"
                            : "=l"(v0), "=l"(v1), "=l"(v2), "=l"(v3)
                            : "l"(sp + e0), "l"(sp + e1), "l"(sp + e2), "l"(sp + e3)
                            : "memory");
                        if ((unsigned)(v0 >> 32) == tgt && (unsigned)(v1 >> 32) == tgt &&
                            (unsigned)(v2 >> 32) == tgt && (unsigned)(v3 >> 32) == tgt) break;
                    }
                    nxt[e3] = __uint_as_float((unsigned)v3);
                } else {
                    for (unsigned it = 0; it < TAG_BOUND; it++) {
                        asm volatile(
                            "ld.relaxed.gpu.global.b64 %0, [%3];\n\t"
                            "ld.relaxed.gpu.global.b64 %1, [%4];\n\t"
                            "ld.relaxed.gpu.global.b64 %2, [%5];"
                            : "=l"(v0), "=l"(v1), "=l"(v2)
                            : "l"(sp + e0), "l"(sp + e1), "l"(sp + e2)
                            : "memory");
                        if ((unsigned)(v0 >> 32) == tgt && (unsigned)(v1 >> 32) == tgt &&
                            (unsigned)(v2 >> 32) == tgt) break;
                    }
                }
                nxt[e0] = __uint_as_float((unsigned)v0);
                nxt[e1] = __uint_as_float((unsigned)v1);
                nxt[e2] = __uint_as_float((unsigned)v2);
            }
            __syncthreads();
        }
    }
}

// ---------------- launch ----------------
extern "C" void kernel_launch(void* const* d_in, const int* in_sizes, int n_in,
                              void* d_out, int out_size)
{
    const int*   word_seq   = (const int*)  d_in[0];
    const int*   pos_seq    = (const int*)  d_in[1];
    const int*   seg_ids    = (const int*)  d_in[2];
    const float* chem       = (const float*)d_in[3];
    const float* word_table = (const float*)d_in[4];
    const float* pos_table  = (const float*)d_in[5];
    const float* Ww         = (const float*)d_in[6];
    const float* Wb         = (const float*)d_in[7];
    const float* Wih1f = (const float*)d_in[8];
    const float* Whh1f = (const float*)d_in[9];
    const float* b1f   = (const float*)d_in[10];
    const float* h01f  = (const float*)d_in[11];
    const float* c01f  = (const float*)d_in[12];
    const float* Wih1b = (const float*)d_in[13];
    const float* Whh1b = (const float*)d_in[14];
    const float* b1b   = (const float*)d_in[15];
    const float* h01b  = (const float*)d_in[16];
    const float* c01b  = (const float*)d_in[17];
    const float* Wih2f = (const float*)d_in[18];
    const float* Whh2f = (const float*)d_in[19];
    const float* b2f   = (const float*)d_in[20];
    const float* h02f  = (const float*)d_in[21];
    const float* c02f  = (const float*)d_in[22];
    const float* Wih2b = (const float*)d_in[23];
    const float* Whh2b = (const float*)d_in[24];
    const float* b2b   = (const float*)d_in[25];
    const float* h02b  = (const float*)d_in[26];
    const float* c02b  = (const float*)d_in[27];

    float* out = (float*)d_out;

    float *ef, *l1, *PF, *PB, *meanp; unsigned long long* hb;
    cudaGetSymbolAddress((void**)&ef,    g_ef);
    cudaGetSymbolAddress((void**)&l1,    g_l1);
    cudaGetSymbolAddress((void**)&PF,    g_PF);
    cudaGetSymbolAddress((void**)&PB,    g_PB);
    cudaGetSymbolAddress((void**)&meanp, g_mean);
    cudaGetSymbolAddress((void**)&hb,    g_hb);

    // (0) mean + starts(bsearch) + hb zero
    k_mean<<<TT, 256>>>(chem, seg_ids);

    // (1) wc = tanh(word_e @ Ww.T + Wb) + mean -> ef[:, :768]; z=1 blocks do pos fill
    k_gemm<<<dim3(6, 32, 2), 256>>>(TT, 768, 300,
        word_table, 300, word_seq,
        Ww, Wb, ef, nullptr, nullptr, nullptr,
        868, meanp, 1, pos_seq, pos_table);

    // (2) layer-1 input projections (both directions)
    k_gemm<<<dim3(13, 32, 2), 256>>>(TT, 1600, 868,
        ef, 868, nullptr,
        Wih1f, b1f, PF,
        Wih1b, b1b, PB,
        1600, nullptr, 0, nullptr, nullptr);

    // (3) layer-1 recurrence
    k_lstm<<<2 * KCTA, NT>>>(
        PF, Whh1f, h01f, c01f, l1, 800, 0,   0, 0, hb + 0 * 2 * HH,
        PB, Whh1b, h01b, c01b, l1, 800, 400, 1, 1, hb + 1 * 2 * HH);

    // (4) layer-2 input projections on l1
    k_gemm<<<dim3(13, 32, 2), 256>>>(TT, 1600, 800,
        l1, 800, nullptr,
        Wih2f, b2f, PF,
        Wih2b, b2b, PB,
        1600, nullptr, 0, nullptr, nullptr);

    // (5) layer-2 recurrence
    k_lstm<<<2 * KCTA, NT>>>(
        PF, Whh2f, h02f, c02f, out,                    400, 0, 0, 0, hb + 2 * 2 * HH,
        PB, Whh2b, h02b, c02b, out + (size_t)TT * 400, 400, 0, 1, 0, hb + 3 * 2 * HH);
}